// round 5
// baseline (speedup 1.0000x reference)
#include <cuda_runtime.h>
#include <cstdint>

// ---------------- problem constants ----------------
#define BATCH_N   1048576
#define IN_SZ     64
#define HID       16
#define KDIM      80          // IN_SZ + HID
#define NDIM      80          // 5 * HID
#define TILE_M    128
#define NTHREADS  128

// smem strides (in floats) chosen for conflict-free mma fragment LDS
#define SA 84                 // A row stride: banks (20*r + c) % 32 all distinct
#define SB 88                 // B row stride: banks (24*k + n) % 32 all distinct

#define A_FLOATS (TILE_M * SA)        // 10752
#define B_FLOATS (KDIM * SB)          // 7040
#define SMEM_FLOATS (A_FLOATS + B_FLOATS + NDIM)
#define SMEM_BYTES  (SMEM_FLOATS * 4) // 71488

static __device__ __forceinline__ uint32_t f2tf32(float f) {
    uint32_t u;
    asm("cvt.rna.tf32.f32 %0, %1;" : "=r"(u) : "f"(f));
    return u;
}

static __device__ __forceinline__ void mma_tf32(float* c, const uint32_t* a,
                                                uint32_t b0, uint32_t b1) {
    asm volatile(
        "mma.sync.aligned.m16n8k8.row.col.f32.tf32.tf32.f32 "
        "{%0,%1,%2,%3}, {%4,%5,%6,%7}, {%8,%9}, {%0,%1,%2,%3};"
        : "+f"(c[0]), "+f"(c[1]), "+f"(c[2]), "+f"(c[3])
        : "r"(a[0]), "r"(a[1]), "r"(a[2]), "r"(a[3]), "r"(b0), "r"(b1));
}

static __device__ __forceinline__ float tanh_fast(float x) {
    float e = __expf(-2.0f * fabsf(x));
    float t = __fdividef(1.0f - e, 1.0f + e);
    return copysignf(t, x);
}
static __device__ __forceinline__ float softplus_fast(float x) {
    return fmaxf(x, 0.0f) + __logf(1.0f + __expf(-fabsf(x)));
}

__global__ void __launch_bounds__(NTHREADS, 3) ctlstm_kernel(
    const float* __restrict__ x,
    const float* __restrict__ h_prev,
    const float* __restrict__ c_prev,
    const float* __restrict__ delta_t,
    const float* __restrict__ W_i, const float* __restrict__ b_i,
    const float* __restrict__ W_f, const float* __restrict__ b_f,
    const float* __restrict__ W_o, const float* __restrict__ b_o,
    const float* __restrict__ W_c, const float* __restrict__ b_c,
    const float* __restrict__ W_d, const float* __restrict__ b_d,
    float* __restrict__ out_h, float* __restrict__ out_c)
{
    extern __shared__ uint32_t smem[];
    uint32_t* As = smem;                    // [128][SA] tf32
    uint32_t* Bs = smem + A_FLOATS;         // [80][SB]  tf32 (W as [k][n])
    float*    bs = reinterpret_cast<float*>(smem + A_FLOATS + B_FLOATS); // bias[80]

    const int tid  = threadIdx.x;
    const int warp = tid >> 5;
    const int lane = tid & 31;
    const int qr   = lane >> 2;   // 0..7
    const int qc   = lane & 3;    // 0..3
    const int row0 = blockIdx.x * TILE_M;

    // ---- fill A: x part [128 rows, cols 0..63] ----
    #pragma unroll
    for (int it = 0; it < (TILE_M * (IN_SZ / 4)) / NTHREADS; it++) {  // 16 iters
        int idx = it * NTHREADS + tid;
        int m = idx >> 4;
        int c4 = idx & 15;
        float4 v = *reinterpret_cast<const float4*>(x + (size_t)(row0 + m) * IN_SZ + c4 * 4);
        uint4 t;
        t.x = f2tf32(v.x); t.y = f2tf32(v.y); t.z = f2tf32(v.z); t.w = f2tf32(v.w);
        *reinterpret_cast<uint4*>(As + m * SA + c4 * 4) = t;
    }
    // ---- fill A: h part [128 rows, cols 64..79] ----
    #pragma unroll
    for (int it = 0; it < (TILE_M * (HID / 4)) / NTHREADS; it++) {    // 4 iters
        int idx = it * NTHREADS + tid;
        int m = idx >> 2;
        int c4 = idx & 3;
        float4 v = *reinterpret_cast<const float4*>(h_prev + (size_t)(row0 + m) * HID + c4 * 4);
        uint4 t;
        t.x = f2tf32(v.x); t.y = f2tf32(v.y); t.z = f2tf32(v.z); t.w = f2tf32(v.w);
        *reinterpret_cast<uint4*>(As + m * SA + IN_SZ + c4 * 4) = t;
    }
    // ---- fill B: B[k][n] = W_g[k][c]  (n = g*16 + c) ----
    for (int i = tid; i < NDIM * KDIM; i += NTHREADS) {               // 50 iters
        int k = i / NDIM;
        int n = i - k * NDIM;
        int g = n >> 4, c = n & 15;
        const float* W = (g == 0) ? W_i : (g == 1) ? W_f : (g == 2) ? W_o
                       : (g == 3) ? W_c : W_d;
        Bs[k * SB + n] = f2tf32(W[k * HID + c]);
    }
    // ---- bias ----
    if (tid < NDIM) {
        int g = tid >> 4, c = tid & 15;
        const float* B = (g == 0) ? b_i : (g == 1) ? b_f : (g == 2) ? b_o
                       : (g == 3) ? b_c : b_d;
        bs[tid] = B[c];
    }
    __syncthreads();

    // ---- prefetch epilogue operands early (overlap with MMA) ----
    // Per thread: rows = row0 + warp*32 + mt*16 + rs*8 + qr  (mt,rs in {0,1})
    // cols j0 = jh*8 + 2*qc  (jh in {0,1}), 2 consecutive floats each
    float2 cpv[2][2][2];
    float  dtv[2][2];
    #pragma unroll
    for (int mt = 0; mt < 2; mt++)
        #pragma unroll
        for (int rs = 0; rs < 2; rs++) {
            size_t row = (size_t)row0 + warp * 32 + mt * 16 + rs * 8 + qr;
            dtv[mt][rs] = delta_t[row];
            #pragma unroll
            for (int jh = 0; jh < 2; jh++) {
                int j0 = jh * 8 + 2 * qc;
                cpv[mt][rs][jh] = *reinterpret_cast<const float2*>(c_prev + row * HID + j0);
            }
        }

    // ---- GEMM: per warp 2 m-tiles x 10 n-tiles x 10 k-tiles of m16n8k8 tf32 ----
    float acc[2][10][4];
    #pragma unroll
    for (int mt = 0; mt < 2; mt++)
        #pragma unroll
        for (int nt = 0; nt < 10; nt++)
            #pragma unroll
            for (int c = 0; c < 4; c++) acc[mt][nt][c] = 0.0f;

    const int mbase = warp * 32;
    #pragma unroll
    for (int kt = 0; kt < 10; kt++) {
        uint32_t a[2][4];
        #pragma unroll
        for (int mt = 0; mt < 2; mt++) {
            int r = mbase + mt * 16 + qr;
            int k = kt * 8 + qc;
            a[mt][0] = As[r * SA + k];
            a[mt][1] = As[(r + 8) * SA + k];
            a[mt][2] = As[r * SA + k + 4];
            a[mt][3] = As[(r + 8) * SA + k + 4];
        }
        #pragma unroll
        for (int nt = 0; nt < 10; nt++) {
            int n = nt * 8 + qr;
            uint32_t b0 = Bs[(kt * 8 + qc) * SB + n];
            uint32_t b1 = Bs[(kt * 8 + qc + 4) * SB + n];
            mma_tf32(acc[0][nt], a[0], b0, b1);
            mma_tf32(acc[1][nt], a[1], b0, b1);
        }
    }

    // ---- bias registers: bias[g*16 + jh*8 + 2*qc + b] ----
    float bv[5][2][2];
    #pragma unroll
    for (int g = 0; g < 5; g++)
        #pragma unroll
        for (int jh = 0; jh < 2; jh++) {
            float2 t = *reinterpret_cast<const float2*>(bs + g * 16 + jh * 8 + 2 * qc);
            bv[g][jh][0] = t.x; bv[g][jh][1] = t.y;
        }

    // ---- epilogue ----
    // z col C = g*16 + jh*8 + 2*qc + b  maps to acc[mt][2*g + jh][rs*2 + b]
    #pragma unroll
    for (int mt = 0; mt < 2; mt++) {
        #pragma unroll
        for (int rs = 0; rs < 2; rs++) {
            size_t row = (size_t)row0 + mbase + mt * 16 + rs * 8 + qr;
            float dt = dtv[mt][rs];
            #pragma unroll
            for (int jh = 0; jh < 2; jh++) {
                float2 cp = cpv[mt][rs][jh];
                float cpin[2] = {cp.x, cp.y};
                float h2[2], c2[2];
                #pragma unroll
                for (int b = 0; b < 2; b++) {
                    float zi = acc[mt][0 + jh][rs * 2 + b] + bv[0][jh][b];
                    float zf = acc[mt][2 + jh][rs * 2 + b] + bv[1][jh][b];
                    float zo = acc[mt][4 + jh][rs * 2 + b] + bv[2][jh][b];
                    float zc = acc[mt][6 + jh][rs * 2 + b] + bv[3][jh][b];
                    float zd = acc[mt][8 + jh][rs * 2 + b] + bv[4][jh][b];
                    float ig = tanh_fast(zi);
                    float fg = tanh_fast(zf);
                    float og = tanh_fast(zo);
                    float ct = tanh_fast(zc);
                    float decay = softplus_fast(zd);
                    float cdec = cpin[b] * __expf(-decay * dt);
                    float cn = fg * cdec + ig * ct;
                    c2[b] = cn;
                    h2[b] = og * tanh_fast(cn);
                }
                int j0 = jh * 8 + 2 * qc;
                *reinterpret_cast<float2*>(out_h + row * HID + j0) = make_float2(h2[0], h2[1]);
                *reinterpret_cast<float2*>(out_c + row * HID + j0) = make_float2(c2[0], c2[1]);
            }
        }
    }
}

extern "C" void kernel_launch(void* const* d_in, const int* in_sizes, int n_in,
                              void* d_out, int out_size) {
    const float* x      = (const float*)d_in[0];
    const float* h_prev = (const float*)d_in[1];
    const float* c_prev = (const float*)d_in[2];
    const float* dt     = (const float*)d_in[3];
    const float* W_i = (const float*)d_in[4];
    const float* b_i = (const float*)d_in[5];
    const float* W_f = (const float*)d_in[6];
    const float* b_f = (const float*)d_in[7];
    const float* W_o = (const float*)d_in[8];
    const float* b_o = (const float*)d_in[9];
    const float* W_c = (const float*)d_in[10];
    const float* b_c = (const float*)d_in[11];
    const float* W_d = (const float*)d_in[12];
    const float* b_d = (const float*)d_in[13];

    float* out_h = (float*)d_out;
    float* out_c = out_h + (size_t)out_size / 2;  // (h_next, c_next) concatenated

    cudaFuncSetAttribute(ctlstm_kernel, cudaFuncAttributeMaxDynamicSharedMemorySize, SMEM_BYTES);

    dim3 grid(BATCH_N / TILE_M);
    ctlstm_kernel<<<grid, NTHREADS, SMEM_BYTES>>>(
        x, h_prev, c_prev, dt,
        W_i, b_i, W_f, b_f, W_o, b_o, W_c, b_c, W_d, b_d,
        out_h, out_c);
}

// round 6
// speedup vs baseline: 2.9264x; 2.9264x over previous
#include <cuda_runtime.h>
#include <cstdint>

// ---------------- problem constants ----------------
#define BATCH_N   1048576
#define IN_SZ     64
#define HID       16
#define KDIM      80          // IN_SZ + HID
#define NDIM      80          // 5 * HID
#define TILE_M    128
#define NTHREADS  256

// smem strides (in floats) chosen for conflict-free mma fragment LDS
#define SA 84                 // A row stride: banks (20*qr + qc) % 32 all distinct
#define SB 88                 // B row stride: banks (24*qc + qr) % 32 all distinct

#define A_FLOATS (TILE_M * SA)        // 10752
#define B_FLOATS (KDIM * SB)          // 7040
#define SMEM_FLOATS (A_FLOATS + B_FLOATS + NDIM)
#define SMEM_BYTES  (SMEM_FLOATS * 4) // 71488

// ---------------- precomputed weights (written by prep kernel) ----------------
__device__ uint32_t g_Bp[B_FLOATS];    // tf32 W as [k][n], stride SB
__device__ float    g_bias[NDIM];

static __device__ __forceinline__ uint32_t f2tf32(float f) {
    uint32_t u;
    asm("cvt.rna.tf32.f32 %0, %1;" : "=r"(u) : "f"(f));
    return u;
}

static __device__ __forceinline__ void mma_tf32(float* c, const uint32_t* a,
                                                uint32_t b0, uint32_t b1) {
    asm volatile(
        "mma.sync.aligned.m16n8k8.row.col.f32.tf32.tf32.f32 "
        "{%0,%1,%2,%3}, {%4,%5,%6,%7}, {%8,%9}, {%0,%1,%2,%3};"
        : "+f"(c[0]), "+f"(c[1]), "+f"(c[2]), "+f"(c[3])
        : "r"(a[0]), "r"(a[1]), "r"(a[2]), "r"(a[3]), "r"(b0), "r"(b1));
}

static __device__ __forceinline__ float tanh_fast(float x) {
    float e = __expf(-2.0f * fabsf(x));
    float t = __fdividef(1.0f - e, 1.0f + e);
    return copysignf(t, x);
}
static __device__ __forceinline__ float softplus_fast(float x) {
    return fmaxf(x, 0.0f) + __logf(1.0f + __expf(-fabsf(x)));
}

// ---------------- prep: pack W -> tf32 [k][n] stride SB, bias ----------------
__global__ void prep_kernel(
    const float* __restrict__ W_i, const float* __restrict__ b_i,
    const float* __restrict__ W_f, const float* __restrict__ b_f,
    const float* __restrict__ W_o, const float* __restrict__ b_o,
    const float* __restrict__ W_c, const float* __restrict__ b_c,
    const float* __restrict__ W_d, const float* __restrict__ b_d)
{
    int idx = blockIdx.x * blockDim.x + threadIdx.x;
    if (idx < NDIM * KDIM) {
        int k = idx / NDIM;
        int n = idx - k * NDIM;
        int g = n >> 4, c = n & 15;
        const float* W = (g == 0) ? W_i : (g == 1) ? W_f : (g == 2) ? W_o
                       : (g == 3) ? W_c : W_d;
        g_Bp[k * SB + n] = f2tf32(W[k * HID + c]);
    } else if (idx < NDIM * KDIM + NDIM) {
        int n = idx - NDIM * KDIM;
        int g = n >> 4, c = n & 15;
        const float* B = (g == 0) ? b_i : (g == 1) ? b_f : (g == 2) ? b_o
                       : (g == 3) ? b_c : b_d;
        g_bias[n] = B[c];
    } else if (idx >= NDIM * KDIM + NDIM && idx < NDIM * KDIM + NDIM + 0) {
        // unreachable
    }
    // zero the pad columns once so the main kernel's vector copy is defined
    if (idx < KDIM) {
        #pragma unroll
        for (int p = NDIM; p < SB; p++) g_Bp[idx * SB + p] = 0u;
    }
}

__global__ void __launch_bounds__(NTHREADS, 3) ctlstm_kernel(
    const float* __restrict__ x,
    const float* __restrict__ h_prev,
    const float* __restrict__ c_prev,
    const float* __restrict__ delta_t,
    float* __restrict__ out_h, float* __restrict__ out_c)
{
    extern __shared__ uint32_t smem[];
    uint32_t* As = smem;                    // [128][SA] tf32
    uint32_t* Bs = smem + A_FLOATS;         // [80][SB]  tf32 (W as [k][n])
    float*    bs = reinterpret_cast<float*>(smem + A_FLOATS + B_FLOATS); // bias[80]

    const int tid  = threadIdx.x;
    const int warp = tid >> 5;
    const int lane = tid & 31;
    const int qr   = lane >> 2;   // 0..7
    const int qc   = lane & 3;    // 0..3
    const int row0 = blockIdx.x * TILE_M;

    // ---- copy B + bias from precomputed globals (coalesced, L2-hot) ----
    {
        const uint4* src = reinterpret_cast<const uint4*>(g_Bp);
        uint4* dst = reinterpret_cast<uint4*>(Bs);
        #pragma unroll
        for (int it = 0; it < B_FLOATS / 4 / NTHREADS + 1; it++) {
            int i = it * NTHREADS + tid;
            if (i < B_FLOATS / 4) dst[i] = src[i];
        }
        if (tid < NDIM) bs[tid] = g_bias[tid];
    }

    // ---- fill A: x part [128 rows, cols 0..63] ----
    #pragma unroll
    for (int it = 0; it < (TILE_M * (IN_SZ / 4)) / NTHREADS; it++) {  // 8 iters
        int idx = it * NTHREADS + tid;
        int m = idx >> 4;
        int c4 = idx & 15;
        float4 v = *reinterpret_cast<const float4*>(x + (size_t)(row0 + m) * IN_SZ + c4 * 4);
        uint4 t;
        t.x = f2tf32(v.x); t.y = f2tf32(v.y); t.z = f2tf32(v.z); t.w = f2tf32(v.w);
        *reinterpret_cast<uint4*>(As + m * SA + c4 * 4) = t;
    }
    // ---- fill A: h part [128 rows, cols 64..79] ----
    #pragma unroll
    for (int it = 0; it < (TILE_M * (HID / 4)) / NTHREADS; it++) {    // 2 iters
        int idx = it * NTHREADS + tid;
        int m = idx >> 2;
        int c4 = idx & 3;
        float4 v = *reinterpret_cast<const float4*>(h_prev + (size_t)(row0 + m) * HID + c4 * 4);
        uint4 t;
        t.x = f2tf32(v.x); t.y = f2tf32(v.y); t.z = f2tf32(v.z); t.w = f2tf32(v.w);
        *reinterpret_cast<uint4*>(As + m * SA + IN_SZ + c4 * 4) = t;
    }

    // ---- prefetch epilogue operands early (overlap with MMA) ----
    // Per thread: rows = row0 + warp*16 + rs*8 + qr (rs in {0,1})
    // cols j0 = jh*8 + 2*qc (jh in {0,1}), 2 consecutive floats each
    float2 cpv[2][2];
    float  dtv[2];
    #pragma unroll
    for (int rs = 0; rs < 2; rs++) {
        size_t row = (size_t)row0 + warp * 16 + rs * 8 + qr;
        dtv[rs] = delta_t[row];
        #pragma unroll
        for (int jh = 0; jh < 2; jh++) {
            int j0 = jh * 8 + 2 * qc;
            cpv[rs][jh] = *reinterpret_cast<const float2*>(c_prev + row * HID + j0);
        }
    }

    __syncthreads();

    // ---- GEMM: per warp 1 m-tile(16 rows) x 10 n-tiles x 10 k-tiles of m16n8k8 ----
    float acc[10][4];
    #pragma unroll
    for (int nt = 0; nt < 10; nt++)
        #pragma unroll
        for (int c = 0; c < 4; c++) acc[nt][c] = 0.0f;

    const int mbase = warp * 16;
    #pragma unroll
    for (int kt = 0; kt < 10; kt++) {
        uint32_t a[4];
        {
            int r = mbase + qr;
            int k = kt * 8 + qc;
            a[0] = As[r * SA + k];
            a[1] = As[(r + 8) * SA + k];
            a[2] = As[r * SA + k + 4];
            a[3] = As[(r + 8) * SA + k + 4];
        }
        #pragma unroll
        for (int nt = 0; nt < 10; nt++) {
            int n = nt * 8 + qr;
            uint32_t b0 = Bs[(kt * 8 + qc) * SB + n];
            uint32_t b1 = Bs[(kt * 8 + qc + 4) * SB + n];
            mma_tf32(acc[nt], a, b0, b1);
        }
    }

    // ---- epilogue ----
    // z col C = g*16 + jh*8 + 2*qc + b  maps to acc[2*g + jh][rs*2 + b]
    #pragma unroll
    for (int rs = 0; rs < 2; rs++) {
        size_t row = (size_t)row0 + mbase + rs * 8 + qr;
        float dt = dtv[rs];
        #pragma unroll
        for (int jh = 0; jh < 2; jh++) {
            float2 cp = cpv[rs][jh];
            float cpin[2] = {cp.x, cp.y};
            float h2[2], c2[2];
            #pragma unroll
            for (int b = 0; b < 2; b++) {
                int C = jh * 8 + 2 * qc + b;
                float zi = acc[0 + jh][rs * 2 + b] + bs[C];
                float zf = acc[2 + jh][rs * 2 + b] + bs[16 + C];
                float zo = acc[4 + jh][rs * 2 + b] + bs[32 + C];
                float zc = acc[6 + jh][rs * 2 + b] + bs[48 + C];
                float zd = acc[8 + jh][rs * 2 + b] + bs[64 + C];
                float ig = tanh_fast(zi);
                float fg = tanh_fast(zf);
                float og = tanh_fast(zo);
                float ct = tanh_fast(zc);
                float decay = softplus_fast(zd);
                float cdec = cpin[b] * __expf(-decay * dt);
                float cn = fg * cdec + ig * ct;
                c2[b] = cn;
                h2[b] = og * tanh_fast(cn);
            }
            int j0 = jh * 8 + 2 * qc;
            *reinterpret_cast<float2*>(out_h + row * HID + j0) = make_float2(h2[0], h2[1]);
            *reinterpret_cast<float2*>(out_c + row * HID + j0) = make_float2(c2[0], c2[1]);
        }
    }
}

extern "C" void kernel_launch(void* const* d_in, const int* in_sizes, int n_in,
                              void* d_out, int out_size) {
    const float* x      = (const float*)d_in[0];
    const float* h_prev = (const float*)d_in[1];
    const float* c_prev = (const float*)d_in[2];
    const float* dt     = (const float*)d_in[3];
    const float* W_i = (const float*)d_in[4];
    const float* b_i = (const float*)d_in[5];
    const float* W_f = (const float*)d_in[6];
    const float* b_f = (const float*)d_in[7];
    const float* W_o = (const float*)d_in[8];
    const float* b_o = (const float*)d_in[9];
    const float* W_c = (const float*)d_in[10];
    const float* b_c = (const float*)d_in[11];
    const float* W_d = (const float*)d_in[12];
    const float* b_d = (const float*)d_in[13];

    float* out_h = (float*)d_out;
    float* out_c = out_h + (size_t)out_size / 2;  // (h_next, c_next) concatenated

    cudaFuncSetAttribute(ctlstm_kernel, cudaFuncAttributeMaxDynamicSharedMemorySize, SMEM_BYTES);

    // one-time weight packing (cheap; graph-capturable, ordered before main)
    prep_kernel<<<(NDIM * KDIM + NDIM + 255) / 256, 256>>>(
        W_i, b_i, W_f, b_f, W_o, b_o, W_c, b_c, W_d, b_d);

    dim3 grid(BATCH_N / TILE_M);
    ctlstm_kernel<<<grid, NTHREADS, SMEM_BYTES>>>(
        x, h_prev, c_prev, dt, out_h, out_c);
}